// round 15
// baseline (speedup 1.0000x reference)
#include <cuda_runtime.h>
#include <cuda_fp16.h>
#include <math.h>
#include <mma.h>
using namespace nvcuda;

#define NN 50000
#define EE 800000
#define DD 96
#define CC 40
#define NITE 8
#define SMOOTH 0.5f

#define NBANDS ((NN + 15) / 16)   // 3125 (NN % 16 == 0)
#define LDW 104                   // padded half ld for W smem
#define LDO 104                   // padded half ld for epilogue staging
#define DBINS 128                 // degree bins for counting sort

// ---------------- scratch (device globals; no allocation allowed) ------------
__device__ __half        g_h16[NN * DD];        // fp16 feature state (sole copy)
__device__ __half        g_W16[DD * DD];        // fp16 W_gc
__device__ unsigned char g_support8[NN * DD];   // e4m3 support (gather source)
__device__ int           g_count[NN];           // zeroed invariant (see out_kernel)
__device__ int           g_rowstart[NN + 1];
__device__ int           g_fill[NN];
__device__ unsigned      g_edge[EE];            // packed: col(u16) | fp16 val << 16
__device__ int           g_dhist[DBINS];        // zeroed invariant (see out_kernel)
__device__ int           g_dbin_start[DBINS];
__device__ int           g_dbin_fill[DBINS];
__device__ int           g_perm[NN];            // degree-sorted row order

// packed f32x2 FMA
__device__ __forceinline__ void ffma2f(float2& d, float2 a, float2 b) {
    unsigned long long dd = *(unsigned long long*)&d;
    asm("fma.rn.f32x2 %0, %1, %2, %0;"
        : "+l"(dd) : "l"(*(unsigned long long*)&a), "l"(*(unsigned long long*)&b));
    d = *(float2*)&dd;
}

// 4x e4m3 (u32) -> two float2
__device__ __forceinline__ void fp8x4_to_f2(unsigned u, float2& f0, float2& f1) {
    unsigned h2a, h2b;
    asm("{ .reg .b16 lo, hi;\n"
        "  mov.b32 {lo, hi}, %2;\n"
        "  cvt.rn.f16x2.e4m3x2 %0, lo;\n"
        "  cvt.rn.f16x2.e4m3x2 %1, hi;\n}"
        : "=r"(h2a), "=r"(h2b) : "r"(u));
    f0 = __half22float2(*(__half2*)&h2a);
    f1 = __half22float2(*(__half2*)&h2b);
}

// two f16x2 (4 halves) -> 4x e4m3 packed u32
__device__ __forceinline__ unsigned f16x4_to_fp8(unsigned h2lo, unsigned h2hi) {
    unsigned u;
    asm("{ .reg .b16 a, b;\n"
        "  cvt.rn.satfinite.e4m3x2.f16x2 a, %1;\n"
        "  cvt.rn.satfinite.e4m3x2.f16x2 b, %2;\n"
        "  mov.b32 %0, {a, b};\n}"
        : "=r"(u) : "r"(h2lo), "r"(h2hi));
    return u;
}

// ---------------- init: h16 = fp16(x) (vectorized), W16 ----------------------
__global__ void init_kernel(const float* __restrict__ x, const float* __restrict__ W) {
    int i = blockIdx.x * blockDim.x + threadIdx.x;
    if (i < NN * DD / 8) {
        float4 a = *(const float4*)&x[i * 8];
        float4 c = *(const float4*)&x[i * 8 + 4];
        __half2 h0 = __floats2half2_rn(a.x, a.y);
        __half2 h1 = __floats2half2_rn(a.z, a.w);
        __half2 h2 = __floats2half2_rn(c.x, c.y);
        __half2 h3 = __floats2half2_rn(c.z, c.w);
        uint4 u;
        u.x = *(unsigned*)&h0; u.y = *(unsigned*)&h1;
        u.z = *(unsigned*)&h2; u.w = *(unsigned*)&h3;
        *(uint4*)&g_h16[i * 8] = u;
    }
    if (i < DD * DD) g_W16[i] = __float2half(W[i]);
}

// ---------------- CSR build (counts pre-zeroed invariant) --------------------
__global__ void hist_kernel(const int* __restrict__ erow) {
    int e = blockIdx.x * blockDim.x + threadIdx.x;
    if (e < EE) atomicAdd(&g_count[erow[e]], 1);
}

__global__ void scan_kernel() {
    __shared__ int part[1024];
    const int CH = (NN + 1023) / 1024;
    int t = threadIdx.x;
    int begin = t * CH;
    int end = begin + CH; if (end > NN) end = NN;
    int s = 0;
    for (int i = begin; i < end; ++i) s += g_count[i];
    part[t] = s;
    __syncthreads();
    for (int off = 1; off < 1024; off <<= 1) {
        int v = (t >= off) ? part[t - off] : 0;
        __syncthreads();
        part[t] += v;
        __syncthreads();
    }
    int running = (t == 0) ? 0 : part[t - 1];
    for (int i = begin; i < end; ++i) {
        g_rowstart[i] = running;
        g_fill[i] = running;
        running += g_count[i];
    }
    if (t == 1023) g_rowstart[NN] = running;  // == EE
}

__global__ void fill_kernel(const int* __restrict__ erow,
                            const int* __restrict__ ecol,
                            const float* __restrict__ ev) {
    int e = blockIdx.x * blockDim.x + threadIdx.x;
    if (e < EE) {
        int r = erow[e];
        int p = atomicAdd(&g_fill[r], 1);
        __half hv = __float2half(ev[e]);
        g_edge[p] = (unsigned)ecol[e]
                  | ((unsigned)__half_as_ushort(hv) << 16);
    }
}

// ---------------- degree-sorted schedule (counting sort) ---------------------
__global__ void deg_hist_kernel() {
    int r = blockIdx.x * blockDim.x + threadIdx.x;
    if (r < NN) {
        int d = g_rowstart[r + 1] - g_rowstart[r];
        if (d > DBINS - 1) d = DBINS - 1;
        atomicAdd(&g_dhist[d], 1);
    }
}

__global__ void dbin_scan_kernel() {
    __shared__ int sh[DBINS];
    int t = threadIdx.x;                 // 128 threads
    sh[t] = g_dhist[t];
    __syncthreads();
    // exclusive scan via inclusive Hillis-Steele
    int val = sh[t];
    for (int off = 1; off < DBINS; off <<= 1) {
        int v = (t >= off) ? sh[t - off] : 0;
        __syncthreads();
        sh[t] += v;
        __syncthreads();
    }
    int excl = sh[t] - val;
    g_dbin_start[t] = excl;
    g_dbin_fill[t] = excl;
}

__global__ void perm_kernel() {
    int r = blockIdx.x * blockDim.x + threadIdx.x;
    if (r < NN) {
        int d = g_rowstart[r + 1] - g_rowstart[r];
        if (d > DBINS - 1) d = DBINS - 1;
        int p = atomicAdd(&g_dbin_fill[d], 1);
        g_perm[p] = r;
    }
}

// ---------------- GEMM: support8 = e4m3(h16 @ W16), tensor cores -------------
__global__ void __launch_bounds__(256) gemm_kernel() {
    __shared__ __half Ws[DD * LDW];      // 19968 B
    __shared__ __half Os[128 * LDO];     // 26624 B
    int tid = threadIdx.x, wid = tid >> 5, lane = tid & 31;
    int band = blockIdx.x * 8 + wid;

    for (int i = tid; i < DD * DD / 8; i += 256) {
        int r = (i * 8) / DD, c = (i * 8) % DD;
        *(uint4*)&Ws[r * LDW + c] = *(const uint4*)&g_W16[r * DD + c];
    }
    __syncthreads();
    if (band >= NBANDS) return;

    wmma::fragment<wmma::matrix_a, 16, 16, 16, __half, wmma::row_major> af[6];
    const __half* Abase = g_h16 + (size_t)band * 16 * DD;
#pragma unroll
    for (int k = 0; k < 6; ++k)
        wmma::load_matrix_sync(af[k], Abase + k * 16, DD);

    wmma::fragment<wmma::accumulator, 16, 16, 16, __half> acc[6];
#pragma unroll
    for (int n = 0; n < 6; ++n) wmma::fill_fragment(acc[n], __float2half(0.f));

#pragma unroll
    for (int k = 0; k < 6; ++k) {
#pragma unroll
        for (int n = 0; n < 6; ++n) {
            wmma::fragment<wmma::matrix_b, 16, 16, 16, __half, wmma::row_major> bf;
            wmma::load_matrix_sync(bf, Ws + (k * 16) * LDW + n * 16, LDW);
            wmma::mma_sync(acc[n], af[k], bf, acc[n]);
        }
    }

    __half* Oband = Os + wid * 16 * LDO;
#pragma unroll
    for (int n = 0; n < 6; ++n)
        wmma::store_matrix_sync(Oband + n * 16, acc[n], LDO, wmma::mem_row_major);
    __syncwarp();

#pragma unroll
    for (int t = 0; t < 12; ++t) {
        int idx = lane + 32 * t;              // 0..383 : 16 rows x 24 u32
        int r = idx / 24, c = idx % 24;
        int grow = band * 16 + r;
        if (grow < NN) {
            unsigned h2lo = *(unsigned*)&Oband[r * LDO + c * 4];
            unsigned h2hi = *(unsigned*)&Oband[r * LDO + c * 4 + 2];
            ((unsigned*)(g_support8 + (size_t)grow * DD))[c] = f16x4_to_fp8(h2lo, h2hi);
        }
    }
}

// ---------------- aggregation + smooth + ReLU --------------------------------
// Warp w processes row g_perm[w] (degree-sorted -> warps in a block have equal
// work, eliminating block-retirement imbalance). Arithmetic per row unchanged.
__global__ void __launch_bounds__(256) agg_kernel(const float* __restrict__ b) {
    int warp = (blockIdx.x * blockDim.x + threadIdx.x) >> 5;
    int lane = threadIdx.x & 31;
    if (warp >= NN) return;
    int row = g_perm[warp];
    int grp = lane >> 3;
    int sub = lane & 7;

    int j0 = g_rowstart[row];
    int j1 = g_rowstart[row + 1];

    float2 acc[6];
#pragma unroll
    for (int i = 0; i < 6; ++i) acc[i] = make_float2(0.f, 0.f);

    for (int j = j0 + grp; j < j1; j += 4) {
        unsigned m = __ldg(&g_edge[j]);
        int col = (int)(m & 0xFFFFu);
        float v = __half2float(__ushort_as_half((unsigned short)(m >> 16)));
        float2 vv = make_float2(v, v);
        const unsigned* s = (const unsigned*)(g_support8 + (size_t)col * DD);
        unsigned d0 = __ldg(&s[sub]);
        unsigned d1 = __ldg(&s[8 + sub]);
        unsigned d2 = __ldg(&s[16 + sub]);
        float2 f0, f1;
        fp8x4_to_f2(d0, f0, f1); ffma2f(acc[0], f0, vv); ffma2f(acc[1], f1, vv);
        fp8x4_to_f2(d1, f0, f1); ffma2f(acc[2], f0, vv); ffma2f(acc[3], f1, vv);
        fp8x4_to_f2(d2, f0, f1); ffma2f(acc[4], f0, vv); ffma2f(acc[5], f1, vv);
    }

#pragma unroll
    for (int i = 0; i < 6; ++i) {
        acc[i].x += __shfl_xor_sync(0xffffffffu, acc[i].x, 8);
        acc[i].y += __shfl_xor_sync(0xffffffffu, acc[i].y, 8);
        acc[i].x += __shfl_xor_sync(0xffffffffu, acc[i].x, 16);
        acc[i].y += __shfl_xor_sync(0xffffffffu, acc[i].y, 16);
    }

    if (lane < 8) {
        __half* hrow = g_h16 + (size_t)row * DD;
#pragma unroll
        for (int sg = 0; sg < 3; ++sg) {
            int off = sg * 32 + sub * 4;
            uint2 hu = *(uint2*)&hrow[off];
            float2 h0 = __half22float2(*(__half2*)&hu.x);
            float2 h1 = __half22float2(*(__half2*)&hu.y);
            float4 bv = *(const float4*)&b[off];
            float2 a0 = acc[2 * sg];
            float2 a1 = acc[2 * sg + 1];
            float r0 = fmaxf(SMOOTH * h0.x + (1.f - SMOOTH) * (a0.x + bv.x), 0.f);
            float r1 = fmaxf(SMOOTH * h0.y + (1.f - SMOOTH) * (a0.y + bv.y), 0.f);
            float r2 = fmaxf(SMOOTH * h1.x + (1.f - SMOOTH) * (a1.x + bv.z), 0.f);
            float r3 = fmaxf(SMOOTH * h1.y + (1.f - SMOOTH) * (a1.y + bv.w), 0.f);
            __half2 p0 = __floats2half2_rn(r0, r1);
            __half2 p1 = __floats2half2_rn(r2, r3);
            uint2 u; u.x = *(unsigned*)&p0; u.y = *(unsigned*)&p1;
            *(uint2*)&hrow[off] = u;
        }
    }
}

// ---------------- final: logits + log_softmax; restore zero invariants -------
__global__ void __launch_bounds__(256) out_kernel(const float* __restrict__ Wl,
                                                  float* __restrict__ out) {
    __shared__ float Ws2[DD * CC];
    __shared__ float Hs[32 * DD];
    __shared__ float Ls[32 * CC];
    int tid = threadIdx.x;
    int row0 = blockIdx.x * 32;

    int gz = blockIdx.x * blockDim.x + tid;
    if (gz < NN) g_count[gz] = 0;
    if (gz < DBINS) g_dhist[gz] = 0;

    for (int i = tid; i < DD * CC; i += 256) Ws2[i] = Wl[i];
    for (int i = tid; i < 32 * DD; i += 256) {
        int r = row0 + i / DD;
        Hs[i] = (r < NN) ? __half2float(g_h16[(size_t)r * DD + (i % DD)]) : 0.f;
    }
    __syncthreads();

    for (int o = tid; o < 32 * CC; o += 256) {
        int r = o / CC, c = o % CC;
        float a = 0.f;
#pragma unroll 4
        for (int k = 0; k < DD; ++k) a += Hs[r * DD + k] * Ws2[k * CC + c];
        Ls[o] = a;
    }
    __syncthreads();

    if (tid < 32) {
        int r = row0 + tid;
        if (r < NN) {
            float m = -1e30f;
#pragma unroll
            for (int c = 0; c < CC; ++c) m = fmaxf(m, Ls[tid * CC + c]);
            float s = 0.f;
#pragma unroll
            for (int c = 0; c < CC; ++c) s += expf(Ls[tid * CC + c] - m);
            float lse = m + logf(s);
#pragma unroll
            for (int c = 0; c < CC; ++c) out[r * CC + c] = Ls[tid * CC + c] - lse;
        }
    }
}

// ---------------- launch ------------------------------------------------------
// Forked-stream capture: CSR build + degree sort run concurrently with
// init + first GEMM; join before the first agg.
extern "C" void kernel_launch(void* const* d_in, const int* in_sizes, int n_in,
                              void* d_out, int out_size) {
    (void)in_sizes; (void)n_in; (void)out_size;
    const float* x    = (const float*)d_in[0];
    const int*   erow = (const int*)d_in[1];
    const int*   ecol = (const int*)d_in[2];
    const float* ev   = (const float*)d_in[3];
    const float* Wgc  = (const float*)d_in[4];
    const float* bgc  = (const float*)d_in[5];
    const float* Wlin = (const float*)d_in[6];
    float* out = (float*)d_out;

    cudaStream_t s2;
    cudaEvent_t evFork, evJoin;
    cudaStreamCreateWithFlags(&s2, cudaStreamNonBlocking);
    cudaEventCreateWithFlags(&evFork, cudaEventDisableTiming);
    cudaEventCreateWithFlags(&evJoin, cudaEventDisableTiming);

    cudaEventRecord(evFork, 0);
    cudaStreamWaitEvent(s2, evFork, 0);
    hist_kernel<<<(EE + 255) / 256, 256, 0, s2>>>(erow);
    scan_kernel<<<1, 1024, 0, s2>>>();
    fill_kernel<<<(EE + 255) / 256, 256, 0, s2>>>(erow, ecol, ev);
    deg_hist_kernel<<<(NN + 255) / 256, 256, 0, s2>>>();
    dbin_scan_kernel<<<1, DBINS, 0, s2>>>();
    perm_kernel<<<(NN + 255) / 256, 256, 0, s2>>>();
    cudaEventRecord(evJoin, s2);

    init_kernel<<<(NN * DD / 8 + 255) / 256, 256>>>(x, Wgc);
    gemm_kernel<<<(NBANDS + 7) / 8, 256>>>();
    cudaStreamWaitEvent(0, evJoin, 0);

    for (int it = 0; it < NITE; ++it) {
        if (it > 0) gemm_kernel<<<(NBANDS + 7) / 8, 256>>>();
        agg_kernel<<<(NN * 32 + 255) / 256, 256>>>(bgc);
    }

    out_kernel<<<(NN + 31) / 32, 256>>>(Wlin, out);

    cudaEventDestroy(evFork);
    cudaEventDestroy(evJoin);
    cudaStreamDestroy(s2);
}

// round 16
// speedup vs baseline: 1.0053x; 1.0053x over previous
#include <cuda_runtime.h>
#include <cuda_fp16.h>
#include <math.h>
#include <mma.h>
using namespace nvcuda;

#define NN 50000
#define EE 800000
#define DD 96
#define CC 40
#define NITE 8
#define SMOOTH 0.5f

#define NBANDS ((NN + 15) / 16)   // 3125 (NN % 16 == 0)
#define LDW 104                   // padded half ld for W smem
#define LDO 104                   // padded half ld for epilogue staging

// ---------------- scratch (device globals; no allocation allowed) ------------
__device__ __half g_h16[NN * DD];        // fp16 feature state (sole copy)
__device__ __half g_W16[DD * DD];        // fp16 W_gc
__device__ uint4  g_support8v[NN * 8];   // e4m3 support, 128B padded rows (24 real + 8 pad u32)
__device__ int    g_count[NN];           // zeroed invariant (see out_kernel)
__device__ int    g_rowstart[NN + 1];
__device__ int    g_fill[NN];
__device__ unsigned g_edge[EE];          // packed: col(u16) | fp16 val << 16

// packed f32x2 FMA
__device__ __forceinline__ void ffma2f(float2& d, float2 a, float2 b) {
    unsigned long long dd = *(unsigned long long*)&d;
    asm("fma.rn.f32x2 %0, %1, %2, %0;"
        : "+l"(dd) : "l"(*(unsigned long long*)&a), "l"(*(unsigned long long*)&b));
    d = *(float2*)&dd;
}

// 4x e4m3 (u32) -> two float2
__device__ __forceinline__ void fp8x4_to_f2(unsigned u, float2& f0, float2& f1) {
    unsigned h2a, h2b;
    asm("{ .reg .b16 lo, hi;\n"
        "  mov.b32 {lo, hi}, %2;\n"
        "  cvt.rn.f16x2.e4m3x2 %0, lo;\n"
        "  cvt.rn.f16x2.e4m3x2 %1, hi;\n}"
        : "=r"(h2a), "=r"(h2b) : "r"(u));
    f0 = __half22float2(*(__half2*)&h2a);
    f1 = __half22float2(*(__half2*)&h2b);
}

// two f16x2 (4 halves) -> 4x e4m3 packed u32
__device__ __forceinline__ unsigned f16x4_to_fp8(unsigned h2lo, unsigned h2hi) {
    unsigned u;
    asm("{ .reg .b16 a, b;\n"
        "  cvt.rn.satfinite.e4m3x2.f16x2 a, %1;\n"
        "  cvt.rn.satfinite.e4m3x2.f16x2 b, %2;\n"
        "  mov.b32 %0, {a, b};\n}"
        : "=r"(u) : "r"(h2lo), "r"(h2hi));
    return u;
}

// ---------------- init: h16 = fp16(x) (vectorized), W16 ----------------------
__global__ void init_kernel(const float* __restrict__ x, const float* __restrict__ W) {
    int i = blockIdx.x * blockDim.x + threadIdx.x;
    if (i < NN * DD / 8) {
        float4 a = *(const float4*)&x[i * 8];
        float4 c = *(const float4*)&x[i * 8 + 4];
        __half2 h0 = __floats2half2_rn(a.x, a.y);
        __half2 h1 = __floats2half2_rn(a.z, a.w);
        __half2 h2 = __floats2half2_rn(c.x, c.y);
        __half2 h3 = __floats2half2_rn(c.z, c.w);
        uint4 u;
        u.x = *(unsigned*)&h0; u.y = *(unsigned*)&h1;
        u.z = *(unsigned*)&h2; u.w = *(unsigned*)&h3;
        *(uint4*)&g_h16[i * 8] = u;
    }
    if (i < DD * DD) g_W16[i] = __float2half(W[i]);
}

// ---------------- CSR build (counts pre-zeroed invariant) --------------------
__global__ void hist_kernel(const int* __restrict__ erow) {
    int e = blockIdx.x * blockDim.x + threadIdx.x;
    if (e < EE) atomicAdd(&g_count[erow[e]], 1);
}

__global__ void scan_kernel() {
    __shared__ int part[1024];
    const int CH = (NN + 1023) / 1024;
    int t = threadIdx.x;
    int begin = t * CH;
    int end = begin + CH; if (end > NN) end = NN;
    int s = 0;
    for (int i = begin; i < end; ++i) s += g_count[i];
    part[t] = s;
    __syncthreads();
    for (int off = 1; off < 1024; off <<= 1) {
        int v = (t >= off) ? part[t - off] : 0;
        __syncthreads();
        part[t] += v;
        __syncthreads();
    }
    int running = (t == 0) ? 0 : part[t - 1];
    for (int i = begin; i < end; ++i) {
        g_rowstart[i] = running;
        g_fill[i] = running;
        running += g_count[i];
    }
    if (t == 1023) g_rowstart[NN] = running;  // == EE
}

__global__ void fill_kernel(const int* __restrict__ erow,
                            const int* __restrict__ ecol,
                            const float* __restrict__ ev) {
    int e = blockIdx.x * blockDim.x + threadIdx.x;
    if (e < EE) {
        int r = erow[e];
        int p = atomicAdd(&g_fill[r], 1);
        __half hv = __float2half(ev[e]);
        g_edge[p] = (unsigned)ecol[e]
                  | ((unsigned)__half_as_ushort(hv) << 16);
    }
}

// ---------------- GEMM: support8 = e4m3(h16 @ W16), tensor cores -------------
// Epilogue writes 128B padded rows: 24 real u32 + 8 zero u32.
__global__ void __launch_bounds__(256) gemm_kernel() {
    __shared__ __half Ws[DD * LDW];      // 19968 B
    __shared__ __half Os[128 * LDO];     // 26624 B
    int tid = threadIdx.x, wid = tid >> 5, lane = tid & 31;
    int band = blockIdx.x * 8 + wid;

    for (int i = tid; i < DD * DD / 8; i += 256) {
        int r = (i * 8) / DD, c = (i * 8) % DD;
        *(uint4*)&Ws[r * LDW + c] = *(const uint4*)&g_W16[r * DD + c];
    }
    __syncthreads();
    if (band >= NBANDS) return;

    wmma::fragment<wmma::matrix_a, 16, 16, 16, __half, wmma::row_major> af[6];
    const __half* Abase = g_h16 + (size_t)band * 16 * DD;
#pragma unroll
    for (int k = 0; k < 6; ++k)
        wmma::load_matrix_sync(af[k], Abase + k * 16, DD);

    wmma::fragment<wmma::accumulator, 16, 16, 16, __half> acc[6];
#pragma unroll
    for (int n = 0; n < 6; ++n) wmma::fill_fragment(acc[n], __float2half(0.f));

#pragma unroll
    for (int k = 0; k < 6; ++k) {
#pragma unroll
        for (int n = 0; n < 6; ++n) {
            wmma::fragment<wmma::matrix_b, 16, 16, 16, __half, wmma::row_major> bf;
            wmma::load_matrix_sync(bf, Ws + (k * 16) * LDW + n * 16, LDW);
            wmma::mma_sync(acc[n], af[k], bf, acc[n]);
        }
    }

    __half* Oband = Os + wid * 16 * LDO;
#pragma unroll
    for (int n = 0; n < 6; ++n)
        wmma::store_matrix_sync(Oband + n * 16, acc[n], LDO, wmma::mem_row_major);
    __syncwarp();

#pragma unroll
    for (int t = 0; t < 16; ++t) {
        int idx = lane + 32 * t;              // 0..511 : 16 rows x 32 u32
        int r = idx >> 5, c = idx & 31;
        int grow = band * 16 + r;
        if (grow < NN) {
            unsigned val = 0u;
            if (c < 24) {
                unsigned h2lo = *(unsigned*)&Oband[r * LDO + c * 4];
                unsigned h2hi = *(unsigned*)&Oband[r * LDO + c * 4 + 2];
                val = f16x4_to_fp8(h2lo, h2hi);
            }
            ((unsigned*)g_support8v)[(size_t)grow * 32 + c] = val;
        }
    }
}

// ---------------- aggregation + smooth + ReLU --------------------------------
// One warp per row; 4 edge-groups x 8 lanes. Each group's 8 lanes fetch the
// edge's 128B support row as ONE LDG.128 (1 line = 1 wavefront per edge).
// Lane sub owns features 16*sub..16*sub+15 (sub<6 real, 6-7 zero pad).
__global__ void __launch_bounds__(256) agg_kernel(const float* __restrict__ b) {
    int warp = (blockIdx.x * blockDim.x + threadIdx.x) >> 5;
    int lane = threadIdx.x & 31;
    if (warp >= NN) return;
    int grp = lane >> 3;
    int sub = lane & 7;

    int j0 = g_rowstart[warp];
    int j1 = g_rowstart[warp + 1];

    float2 acc[8];
#pragma unroll
    for (int i = 0; i < 8; ++i) acc[i] = make_float2(0.f, 0.f);

    for (int j = j0 + grp; j < j1; j += 4) {
        unsigned m = __ldg(&g_edge[j]);
        int col = (int)(m & 0xFFFFu);
        float v = __half2float(__ushort_as_half((unsigned short)(m >> 16)));
        float2 vv = make_float2(v, v);
        uint4 d = __ldg(&g_support8v[(size_t)col * 8 + sub]);   // 16B of the row
        float2 f0, f1;
        fp8x4_to_f2(d.x, f0, f1); ffma2f(acc[0], f0, vv); ffma2f(acc[1], f1, vv);
        fp8x4_to_f2(d.y, f0, f1); ffma2f(acc[2], f0, vv); ffma2f(acc[3], f1, vv);
        fp8x4_to_f2(d.z, f0, f1); ffma2f(acc[4], f0, vv); ffma2f(acc[5], f1, vv);
        fp8x4_to_f2(d.w, f0, f1); ffma2f(acc[6], f0, vv); ffma2f(acc[7], f1, vv);
    }

    // fold the 4 edge-groups (lanes sub, sub+8, sub+16, sub+24)
#pragma unroll
    for (int i = 0; i < 8; ++i) {
        acc[i].x += __shfl_xor_sync(0xffffffffu, acc[i].x, 8);
        acc[i].y += __shfl_xor_sync(0xffffffffu, acc[i].y, 8);
        acc[i].x += __shfl_xor_sync(0xffffffffu, acc[i].x, 16);
        acc[i].y += __shfl_xor_sync(0xffffffffu, acc[i].y, 16);
    }

    if (lane < 6) {   // lanes 0..5 hold the 96 real features (16 each)
        __half* hrow = g_h16 + (size_t)warp * DD + 16 * lane;
        const float* brow = b + 16 * lane;
#pragma unroll
        for (int q = 0; q < 4; ++q) {
            uint2 hu = *(uint2*)&hrow[4 * q];
            float2 h0 = __half22float2(*(__half2*)&hu.x);
            float2 h1 = __half22float2(*(__half2*)&hu.y);
            float4 bv = *(const float4*)&brow[4 * q];
            float2 a0 = acc[2 * q];
            float2 a1 = acc[2 * q + 1];
            float r0 = fmaxf(SMOOTH * h0.x + (1.f - SMOOTH) * (a0.x + bv.x), 0.f);
            float r1 = fmaxf(SMOOTH * h0.y + (1.f - SMOOTH) * (a0.y + bv.y), 0.f);
            float r2 = fmaxf(SMOOTH * h1.x + (1.f - SMOOTH) * (a1.x + bv.z), 0.f);
            float r3 = fmaxf(SMOOTH * h1.y + (1.f - SMOOTH) * (a1.y + bv.w), 0.f);
            __half2 p0 = __floats2half2_rn(r0, r1);
            __half2 p1 = __floats2half2_rn(r2, r3);
            uint2 u; u.x = *(unsigned*)&p0; u.y = *(unsigned*)&p1;
            *(uint2*)&hrow[4 * q] = u;
        }
    }
}

// ---------------- final: logits + log_softmax; re-zero counts for next replay
__global__ void __launch_bounds__(256) out_kernel(const float* __restrict__ Wl,
                                                  float* __restrict__ out) {
    __shared__ float Ws2[DD * CC];
    __shared__ float Hs[32 * DD];
    __shared__ float Ls[32 * CC];
    int tid = threadIdx.x;
    int row0 = blockIdx.x * 32;

    int gz = blockIdx.x * blockDim.x + tid;
    if (gz < NN) g_count[gz] = 0;

    for (int i = tid; i < DD * CC; i += 256) Ws2[i] = Wl[i];
    for (int i = tid; i < 32 * DD; i += 256) {
        int r = row0 + i / DD;
        Hs[i] = (r < NN) ? __half2float(g_h16[(size_t)r * DD + (i % DD)]) : 0.f;
    }
    __syncthreads();

    for (int o = tid; o < 32 * CC; o += 256) {
        int r = o / CC, c = o % CC;
        float a = 0.f;
#pragma unroll 4
        for (int k = 0; k < DD; ++k) a += Hs[r * DD + k] * Ws2[k * CC + c];
        Ls[o] = a;
    }
    __syncthreads();

    if (tid < 32) {
        int r = row0 + tid;
        if (r < NN) {
            float m = -1e30f;
#pragma unroll
            for (int c = 0; c < CC; ++c) m = fmaxf(m, Ls[tid * CC + c]);
            float s = 0.f;
#pragma unroll
            for (int c = 0; c < CC; ++c) s += expf(Ls[tid * CC + c] - m);
            float lse = m + logf(s);
#pragma unroll
            for (int c = 0; c < CC; ++c) out[r * CC + c] = Ls[tid * CC + c] - lse;
        }
    }
}

// ---------------- launch ------------------------------------------------------
// Forked-stream capture: CSR build runs concurrently with init + first GEMM.
extern "C" void kernel_launch(void* const* d_in, const int* in_sizes, int n_in,
                              void* d_out, int out_size) {
    (void)in_sizes; (void)n_in; (void)out_size;
    const float* x    = (const float*)d_in[0];
    const int*   erow = (const int*)d_in[1];
    const int*   ecol = (const int*)d_in[2];
    const float* ev   = (const float*)d_in[3];
    const float* Wgc  = (const float*)d_in[4];
    const float* bgc  = (const float*)d_in[5];
    const float* Wlin = (const float*)d_in[6];
    float* out = (float*)d_out;

    cudaStream_t s2;
    cudaEvent_t evFork, evJoin;
    cudaStreamCreateWithFlags(&s2, cudaStreamNonBlocking);
    cudaEventCreateWithFlags(&evFork, cudaEventDisableTiming);
    cudaEventCreateWithFlags(&evJoin, cudaEventDisableTiming);

    cudaEventRecord(evFork, 0);
    cudaStreamWaitEvent(s2, evFork, 0);
    hist_kernel<<<(EE + 255) / 256, 256, 0, s2>>>(erow);
    scan_kernel<<<1, 1024, 0, s2>>>();
    fill_kernel<<<(EE + 255) / 256, 256, 0, s2>>>(erow, ecol, ev);
    cudaEventRecord(evJoin, s2);

    init_kernel<<<(NN * DD / 8 + 255) / 256, 256>>>(x, Wgc);
    gemm_kernel<<<(NBANDS + 7) / 8, 256>>>();
    cudaStreamWaitEvent(0, evJoin, 0);

    for (int it = 0; it < NITE; ++it) {
        if (it > 0) gemm_kernel<<<(NBANDS + 7) / 8, 256>>>();
        agg_kernel<<<(NN * 32 + 255) / 256, 256>>>(bgc);
    }

    out_kernel<<<(NN + 31) / 32, 256>>>(Wlin, out);

    cudaEventDestroy(evFork);
    cudaEventDestroy(evJoin);
    cudaStreamDestroy(s2);
}

// round 17
// speedup vs baseline: 1.2428x; 1.2362x over previous
#include <cuda_runtime.h>
#include <cuda_fp16.h>
#include <math.h>
#include <mma.h>
using namespace nvcuda;

#define NN 50000
#define EE 800000
#define DD 96
#define CC 40
#define NITE 8
#define SMOOTH 0.5f

#define NBANDS ((NN + 15) / 16)   // 3125 (NN % 16 == 0)
#define LDW 104                   // padded half ld for W smem
#define LDO 104                   // padded half ld for epilogue staging
#define CCP 48                    // Wlin cols padded to 48 (3 wmma n-frags)
#define LDB 56                    // padded half ld for Wlin smem
#define LDL 52                    // padded float ld for logits smem

// ---------------- scratch (device globals; no allocation allowed) ------------
__device__ __half        g_h16[NN * DD];        // fp16 feature state (sole copy)
__device__ __half        g_W16[DD * DD];        // fp16 W_gc
__device__ __half        g_Wl16[DD * CCP];      // fp16 Wlin, cols 40..47 zero (static)
__device__ unsigned char g_support8[NN * DD];   // e4m3 support (gather source)
__device__ int           g_count[NN];           // zeroed invariant (see out_kernel)
__device__ int           g_rowstart[NN + 1];
__device__ int           g_fill[NN];
__device__ unsigned      g_edge[EE];            // packed: col(u16) | fp16 val << 16

// packed f32x2 FMA
__device__ __forceinline__ void ffma2f(float2& d, float2 a, float2 b) {
    unsigned long long dd = *(unsigned long long*)&d;
    asm("fma.rn.f32x2 %0, %1, %2, %0;"
        : "+l"(dd) : "l"(*(unsigned long long*)&a), "l"(*(unsigned long long*)&b));
    d = *(float2*)&dd;
}

// 4x e4m3 (u32) -> two float2
__device__ __forceinline__ void fp8x4_to_f2(unsigned u, float2& f0, float2& f1) {
    unsigned h2a, h2b;
    asm("{ .reg .b16 lo, hi;\n"
        "  mov.b32 {lo, hi}, %2;\n"
        "  cvt.rn.f16x2.e4m3x2 %0, lo;\n"
        "  cvt.rn.f16x2.e4m3x2 %1, hi;\n}"
        : "=r"(h2a), "=r"(h2b) : "r"(u));
    f0 = __half22float2(*(__half2*)&h2a);
    f1 = __half22float2(*(__half2*)&h2b);
}

// two f16x2 (4 halves) -> 4x e4m3 packed u32
__device__ __forceinline__ unsigned f16x4_to_fp8(unsigned h2lo, unsigned h2hi) {
    unsigned u;
    asm("{ .reg .b16 a, b;\n"
        "  cvt.rn.satfinite.e4m3x2.f16x2 a, %1;\n"
        "  cvt.rn.satfinite.e4m3x2.f16x2 b, %2;\n"
        "  mov.b32 %0, {a, b};\n}"
        : "=r"(u) : "r"(h2lo), "r"(h2hi));
    return u;
}

// ---------------- init: h16 = fp16(x), W16, Wl16 ------------------------------
__global__ void init_kernel(const float* __restrict__ x, const float* __restrict__ W,
                            const float* __restrict__ Wl) {
    int i = blockIdx.x * blockDim.x + threadIdx.x;
    if (i < NN * DD / 8) {
        float4 a = *(const float4*)&x[i * 8];
        float4 c = *(const float4*)&x[i * 8 + 4];
        __half2 h0 = __floats2half2_rn(a.x, a.y);
        __half2 h1 = __floats2half2_rn(a.z, a.w);
        __half2 h2 = __floats2half2_rn(c.x, c.y);
        __half2 h3 = __floats2half2_rn(c.z, c.w);
        uint4 u;
        u.x = *(unsigned*)&h0; u.y = *(unsigned*)&h1;
        u.z = *(unsigned*)&h2; u.w = *(unsigned*)&h3;
        *(uint4*)&g_h16[i * 8] = u;
    }
    if (i < DD * DD) g_W16[i] = __float2half(W[i]);
    if (i < DD * CC) {
        int r = i / CC, c = i % CC;
        g_Wl16[r * CCP + c] = __float2half(Wl[i]);  // cols 40..47 stay zero
    }
}

// ---------------- CSR build (counts pre-zeroed invariant) --------------------
__global__ void hist_kernel(const int* __restrict__ erow) {
    int e = blockIdx.x * blockDim.x + threadIdx.x;
    if (e < EE) atomicAdd(&g_count[erow[e]], 1);
}

__global__ void scan_kernel() {
    __shared__ int part[1024];
    const int CH = (NN + 1023) / 1024;
    int t = threadIdx.x;
    int begin = t * CH;
    int end = begin + CH; if (end > NN) end = NN;
    int s = 0;
    for (int i = begin; i < end; ++i) s += g_count[i];
    part[t] = s;
    __syncthreads();
    for (int off = 1; off < 1024; off <<= 1) {
        int v = (t >= off) ? part[t - off] : 0;
        __syncthreads();
        part[t] += v;
        __syncthreads();
    }
    int running = (t == 0) ? 0 : part[t - 1];
    for (int i = begin; i < end; ++i) {
        g_rowstart[i] = running;
        g_fill[i] = running;
        running += g_count[i];
    }
    if (t == 1023) g_rowstart[NN] = running;  // == EE
}

__global__ void fill_kernel(const int* __restrict__ erow,
                            const int* __restrict__ ecol,
                            const float* __restrict__ ev) {
    int e = blockIdx.x * blockDim.x + threadIdx.x;
    if (e < EE) {
        int r = erow[e];
        int p = atomicAdd(&g_fill[r], 1);
        __half hv = __float2half(ev[e]);
        g_edge[p] = (unsigned)ecol[e]
                  | ((unsigned)__half_as_ushort(hv) << 16);
    }
}

// ---------------- GEMM: support8 = e4m3(h16 @ W16), tensor cores (R14) -------
__global__ void __launch_bounds__(256) gemm_kernel() {
    __shared__ __half Ws[DD * LDW];      // 19968 B
    __shared__ __half Os[128 * LDO];     // 26624 B
    int tid = threadIdx.x, wid = tid >> 5, lane = tid & 31;
    int band = blockIdx.x * 8 + wid;

    for (int i = tid; i < DD * DD / 8; i += 256) {
        int r = (i * 8) / DD, c = (i * 8) % DD;
        *(uint4*)&Ws[r * LDW + c] = *(const uint4*)&g_W16[r * DD + c];
    }
    __syncthreads();
    if (band >= NBANDS) return;

    wmma::fragment<wmma::matrix_a, 16, 16, 16, __half, wmma::row_major> af[6];
    const __half* Abase = g_h16 + (size_t)band * 16 * DD;
#pragma unroll
    for (int k = 0; k < 6; ++k)
        wmma::load_matrix_sync(af[k], Abase + k * 16, DD);

    wmma::fragment<wmma::accumulator, 16, 16, 16, __half> acc[6];
#pragma unroll
    for (int n = 0; n < 6; ++n) wmma::fill_fragment(acc[n], __float2half(0.f));

#pragma unroll
    for (int k = 0; k < 6; ++k) {
#pragma unroll
        for (int n = 0; n < 6; ++n) {
            wmma::fragment<wmma::matrix_b, 16, 16, 16, __half, wmma::row_major> bf;
            wmma::load_matrix_sync(bf, Ws + (k * 16) * LDW + n * 16, LDW);
            wmma::mma_sync(acc[n], af[k], bf, acc[n]);
        }
    }

    __half* Oband = Os + wid * 16 * LDO;
#pragma unroll
    for (int n = 0; n < 6; ++n)
        wmma::store_matrix_sync(Oband + n * 16, acc[n], LDO, wmma::mem_row_major);
    __syncwarp();

#pragma unroll
    for (int t = 0; t < 12; ++t) {
        int idx = lane + 32 * t;              // 0..383 : 16 rows x 24 u32
        int r = idx / 24, c = idx % 24;
        int grow = band * 16 + r;
        if (grow < NN) {
            unsigned h2lo = *(unsigned*)&Oband[r * LDO + c * 4];
            unsigned h2hi = *(unsigned*)&Oband[r * LDO + c * 4 + 2];
            ((unsigned*)(g_support8 + (size_t)grow * DD))[c] = f16x4_to_fp8(h2lo, h2hi);
        }
    }
}

// ---------------- aggregation + smooth + ReLU (R14 body — the proven floor) --
__global__ void __launch_bounds__(256) agg_kernel(const float* __restrict__ b) {
    int warp = (blockIdx.x * blockDim.x + threadIdx.x) >> 5;
    int lane = threadIdx.x & 31;
    if (warp >= NN) return;
    int grp = lane >> 3;
    int sub = lane & 7;

    int j0 = g_rowstart[warp];
    int j1 = g_rowstart[warp + 1];

    float2 acc[6];
#pragma unroll
    for (int i = 0; i < 6; ++i) acc[i] = make_float2(0.f, 0.f);

    for (int j = j0 + grp; j < j1; j += 4) {
        unsigned m = __ldg(&g_edge[j]);
        int col = (int)(m & 0xFFFFu);
        float v = __half2float(__ushort_as_half((unsigned short)(m >> 16)));
        float2 vv = make_float2(v, v);
        const unsigned* s = (const unsigned*)(g_support8 + (size_t)col * DD);
        unsigned d0 = __ldg(&s[sub]);
        unsigned d1 = __ldg(&s[8 + sub]);
        unsigned d2 = __ldg(&s[16 + sub]);
        float2 f0, f1;
        fp8x4_to_f2(d0, f0, f1); ffma2f(acc[0], f0, vv); ffma2f(acc[1], f1, vv);
        fp8x4_to_f2(d1, f0, f1); ffma2f(acc[2], f0, vv); ffma2f(acc[3], f1, vv);
        fp8x4_to_f2(d2, f0, f1); ffma2f(acc[4], f0, vv); ffma2f(acc[5], f1, vv);
    }

#pragma unroll
    for (int i = 0; i < 6; ++i) {
        acc[i].x += __shfl_xor_sync(0xffffffffu, acc[i].x, 8);
        acc[i].y += __shfl_xor_sync(0xffffffffu, acc[i].y, 8);
        acc[i].x += __shfl_xor_sync(0xffffffffu, acc[i].x, 16);
        acc[i].y += __shfl_xor_sync(0xffffffffu, acc[i].y, 16);
    }

    if (lane < 8) {
        __half* hrow = g_h16 + (size_t)warp * DD;
#pragma unroll
        for (int sg = 0; sg < 3; ++sg) {
            int off = sg * 32 + sub * 4;
            uint2 hu = *(uint2*)&hrow[off];
            float2 h0 = __half22float2(*(__half2*)&hu.x);
            float2 h1 = __half22float2(*(__half2*)&hu.y);
            float4 bv = *(const float4*)&b[off];
            float2 a0 = acc[2 * sg];
            float2 a1 = acc[2 * sg + 1];
            float r0 = fmaxf(SMOOTH * h0.x + (1.f - SMOOTH) * (a0.x + bv.x), 0.f);
            float r1 = fmaxf(SMOOTH * h0.y + (1.f - SMOOTH) * (a0.y + bv.y), 0.f);
            float r2 = fmaxf(SMOOTH * h1.x + (1.f - SMOOTH) * (a1.x + bv.z), 0.f);
            float r3 = fmaxf(SMOOTH * h1.y + (1.f - SMOOTH) * (a1.y + bv.w), 0.f);
            __half2 p0 = __floats2half2_rn(r0, r1);
            __half2 p1 = __floats2half2_rn(r2, r3);
            uint2 u; u.x = *(unsigned*)&p0; u.y = *(unsigned*)&p1;
            *(uint2*)&hrow[off] = u;
        }
    }
}

// ---------------- final: tensor-core logits + parallel log_softmax -----------
// 8 warps/block, warp = 16-row band x 48 cols (cols 40..47 are zero pad).
// fp32 wmma accumulators -> smem; softmax with 2 lanes per row (20 cols each).
__global__ void __launch_bounds__(256) out_kernel(float* __restrict__ out) {
    __shared__ __half Wl[DD * LDB];      // 10752 B
    __shared__ float  Ls[128 * LDL];     // 26624 B
    int tid = threadIdx.x, wid = tid >> 5, lane = tid & 31;
    int band = blockIdx.x * 8 + wid;

    // restore g_count==0 invariant for the next replay
    int gz = blockIdx.x * blockDim.x + tid;
    for (int z = gz; z < NN; z += 391 * 256) g_count[z] = 0;

    // stage Wl16 (96 x 48 halves -> padded stride 56)
    for (int i = tid; i < DD * CCP / 8; i += 256) {
        int r = (i * 8) / CCP, c = (i * 8) % CCP;
        *(uint4*)&Wl[r * LDB + c] = *(const uint4*)&g_Wl16[r * CCP + c];
    }
    __syncthreads();
    if (band >= NBANDS) return;

    wmma::fragment<wmma::accumulator, 16, 16, 16, float> acc[3];
#pragma unroll
    for (int n = 0; n < 3; ++n) wmma::fill_fragment(acc[n], 0.f);

    const __half* Abase = g_h16 + (size_t)band * 16 * DD;
#pragma unroll
    for (int k = 0; k < 6; ++k) {
        wmma::fragment<wmma::matrix_a, 16, 16, 16, __half, wmma::row_major> af;
        wmma::load_matrix_sync(af, Abase + k * 16, DD);
#pragma unroll
        for (int n = 0; n < 3; ++n) {
            wmma::fragment<wmma::matrix_b, 16, 16, 16, __half, wmma::row_major> bf;
            wmma::load_matrix_sync(bf, Wl + (k * 16) * LDB + n * 16, LDB);
            wmma::mma_sync(acc[n], af, bf, acc[n]);
        }
    }

    float* Lband = Ls + wid * 16 * LDL;
#pragma unroll
    for (int n = 0; n < 3; ++n)
        wmma::store_matrix_sync(Lband + n * 16, acc[n], LDL, wmma::mem_row_major);
    __syncwarp();

    // softmax: 2 lanes per row, 20 cols each
    int r = lane >> 1;
    int half = lane & 1;
    const float* Lrow = Lband + r * LDL + half * 20;
    float m = -1e30f;
#pragma unroll
    for (int c = 0; c < 20; ++c) m = fmaxf(m, Lrow[c]);
    m = fmaxf(m, __shfl_xor_sync(0xffffffffu, m, 1));
    float s = 0.f;
#pragma unroll
    for (int c = 0; c < 20; ++c) s += expf(Lrow[c] - m);
    s += __shfl_xor_sync(0xffffffffu, s, 1);
    float lse = m + logf(s);

    int grow = band * 16 + r;
    if (grow < NN) {
        float* orow = out + (size_t)grow * CC + half * 20;
#pragma unroll
        for (int c = 0; c < 20; ++c) orow[c] = Lrow[c] - lse;
    }
}

// ---------------- launch ------------------------------------------------------
// Forked-stream capture: CSR build runs concurrently with init + first GEMM.
extern "C" void kernel_launch(void* const* d_in, const int* in_sizes, int n_in,
                              void* d_out, int out_size) {
    (void)in_sizes; (void)n_in; (void)out_size;
    const float* x    = (const float*)d_in[0];
    const int*   erow = (const int*)d_in[1];
    const int*   ecol = (const int*)d_in[2];
    const float* ev   = (const float*)d_in[3];
    const float* Wgc  = (const float*)d_in[4];
    const float* bgc  = (const float*)d_in[5];
    const float* Wlin = (const float*)d_in[6];
    float* out = (float*)d_out;

    cudaStream_t s2;
    cudaEvent_t evFork, evJoin;
    cudaStreamCreateWithFlags(&s2, cudaStreamNonBlocking);
    cudaEventCreateWithFlags(&evFork, cudaEventDisableTiming);
    cudaEventCreateWithFlags(&evJoin, cudaEventDisableTiming);

    cudaEventRecord(evFork, 0);
    cudaStreamWaitEvent(s2, evFork, 0);
    hist_kernel<<<(EE + 255) / 256, 256, 0, s2>>>(erow);
    scan_kernel<<<1, 1024, 0, s2>>>();
    fill_kernel<<<(EE + 255) / 256, 256, 0, s2>>>(erow, ecol, ev);
    cudaEventRecord(evJoin, s2);

    init_kernel<<<(NN * DD / 8 + 255) / 256, 256>>>(x, Wgc, Wlin);
    gemm_kernel<<<(NBANDS + 7) / 8, 256>>>();
    cudaStreamWaitEvent(0, evJoin, 0);

    for (int it = 0; it < NITE; ++it) {
        if (it > 0) gemm_kernel<<<(NBANDS + 7) / 8, 256>>>();
        agg_kernel<<<(NN * 32 + 255) / 256, 256>>>(bgc);
    }

    out_kernel<<<(NBANDS + 7) / 8, 256>>>(out);

    cudaEventDestroy(evFork);
    cudaEventDestroy(evJoin);
    cudaStreamDestroy(s2);
}